// round 1
// baseline (speedup 1.0000x reference)
#include <cuda_runtime.h>

// out[m,n] = x[m,n] * (sum_k x[m,k] * W[n,k]) + bias[n]
// M=1024, N=512, K=512, all fp32 row-major.

#define M_DIM 1024
#define N_DIM 512
#define K_DIM 512

#define BM 64
#define BN 64
#define BK 16
#define TM 4
#define TN 4
#define NTHREADS 256

__global__ __launch_bounds__(NTHREADS, 1)
void filp_kernel(const float* __restrict__ X,
                 const float* __restrict__ W,
                 const float* __restrict__ bias,
                 float* __restrict__ out)
{
    // Padded to kill bank conflicts on the transposed stores.
    __shared__ float As[BK][BM + 1];
    __shared__ float Bs[BK][BN + 1];

    const int tid = threadIdx.x;     // 0..255
    const int tx  = tid & 15;        // N direction (16)
    const int ty  = tid >> 4;        // M direction (16)

    const int m0 = blockIdx.y * BM;
    const int n0 = blockIdx.x * BN;

    // Loader mapping: each thread loads one float4 of A and one of B per k-step.
    const int lr = tid >> 2;          // 0..63: row within tile
    const int lc = (tid & 3) * 4;     // 0,4,8,12: col within BK

    float acc[TM][TN];
    #pragma unroll
    for (int i = 0; i < TM; i++)
        #pragma unroll
        for (int j = 0; j < TN; j++)
            acc[i][j] = 0.0f;

    const float* aPtr = X + (m0 + lr) * K_DIM + lc;
    const float* bPtr = W + (n0 + lr) * K_DIM + lc;

    for (int k0 = 0; k0 < K_DIM; k0 += BK) {
        float4 av = *reinterpret_cast<const float4*>(aPtr + k0);
        float4 bv = *reinterpret_cast<const float4*>(bPtr + k0);

        As[lc + 0][lr] = av.x;
        As[lc + 1][lr] = av.y;
        As[lc + 2][lr] = av.z;
        As[lc + 3][lr] = av.w;
        Bs[lc + 0][lr] = bv.x;
        Bs[lc + 1][lr] = bv.y;
        Bs[lc + 2][lr] = bv.z;
        Bs[lc + 3][lr] = bv.w;

        __syncthreads();

        #pragma unroll
        for (int k = 0; k < BK; k++) {
            float ra[TM], rb[TN];
            #pragma unroll
            for (int i = 0; i < TM; i++) ra[i] = As[k][ty + i * 16];
            #pragma unroll
            for (int j = 0; j < TN; j++) rb[j] = Bs[k][tx + j * 16];
            #pragma unroll
            for (int i = 0; i < TM; i++)
                #pragma unroll
                for (int j = 0; j < TN; j++)
                    acc[i][j] = fmaf(ra[i], rb[j], acc[i][j]);
        }

        __syncthreads();
    }

    // Fused epilogue: out = x * wx + bias
    #pragma unroll
    for (int j = 0; j < TN; j++) {
        const int n = n0 + tx + j * 16;
        const float bv = __ldg(&bias[n]);
        #pragma unroll
        for (int i = 0; i < TM; i++) {
            const int m = m0 + ty + i * 16;
            const float xv = X[m * K_DIM + n];
            out[m * N_DIM + n] = fmaf(xv, acc[i][j], bv);
        }
    }
}

extern "C" void kernel_launch(void* const* d_in, const int* in_sizes, int n_in,
                              void* d_out, int out_size) {
    const float* x    = (const float*)d_in[0];   // (1024, 512)
    const float* w    = (const float*)d_in[1];   // (512, 512)
    const float* bias = (const float*)d_in[2];   // (512,)
    float* out        = (float*)d_out;           // (1024, 512)

    dim3 grid(N_DIM / BN, M_DIM / BM);   // (8, 16) = 128 CTAs
    filp_kernel<<<grid, NTHREADS>>>(x, w, bias, out);
}

// round 2
// speedup vs baseline: 1.0458x; 1.0458x over previous
#include <cuda_runtime.h>
#include <cstdint>

// out[m,n] = x[m,n] * (sum_k x[m,k] * W[n,k]) + bias[n]
// M=1024, N=512, K=512, fp32 row-major.

#define M_DIM 1024
#define N_DIM 512
#define K_DIM 512

#define BM 64
#define BN 64
#define BK 16
#define NTHREADS 256
#define NCHUNKS (K_DIM / BK)   // 32

__device__ __forceinline__ void fma2(unsigned long long& d,
                                     unsigned long long a,
                                     unsigned long long b) {
    // packed 2x fp32 fma: d.lo += a.lo*b.lo ; d.hi += a.hi*b.hi
    asm("fma.rn.f32x2 %0, %1, %2, %0;" : "+l"(d) : "l"(a), "l"(b));
}

__global__ __launch_bounds__(NTHREADS, 1)
void filp_kernel(const float* __restrict__ X,
                 const float* __restrict__ W,
                 const float* __restrict__ bias,
                 float* __restrict__ out)
{
    // A tile stored DUPLICATED along M: As2[k][2*m] == As2[k][2*m+1] == A[m][k].
    // An LDS.128 then yields two ready-made (a,a) f32x2 operands — no pack MOVs.
    __shared__ float As2[2][BK][2 * BM];   // 2 * 16 * 128 * 4B = 16 KB
    __shared__ float Bs [2][BK][BN];       // 2 * 16 *  64 * 4B =  8 KB

    const int tid = threadIdx.x;
    const int tx  = tid & 15;   // n direction: n = 4*tx .. 4*tx+3
    const int ty  = tid >> 4;   // m direction: m = 4*ty .. 4*ty+3

    const int m0 = blockIdx.y * BM;
    const int n0 = blockIdx.x * BN;

    // Loader: each thread owns one (row, 4-col) float4 of each tile per chunk.
    const int lrow = tid & 63;          // 0..63
    const int lc   = (tid >> 6) * 4;    // 0,4,8,12

    const float4* aG = reinterpret_cast<const float4*>(X + (m0 + lrow) * K_DIM + lc);
    const float4* bG = reinterpret_cast<const float4*>(W + (n0 + lrow) * K_DIM + lc);

    unsigned long long acc[4][2];
    #pragma unroll
    for (int i = 0; i < 4; i++) { acc[i][0] = 0ULL; acc[i][1] = 0ULL; }

    // ---- prologue: chunk 0 -> buffer 0 ----
    {
        float4 av = aG[0];
        float4 bv = bG[0];
        #pragma unroll
        for (int i = 0; i < 4; i++) {
            float va = (&av.x)[i];
            *reinterpret_cast<float2*>(&As2[0][lc + i][2 * lrow]) = make_float2(va, va);
            Bs[0][lc + i][lrow] = (&bv.x)[i];
        }
    }
    __syncthreads();

    int buf = 0;
    for (int t = 1; t < NCHUNKS; ++t) {
        // prefetch next chunk (overlaps with compute below)
        float4 av = aG[t * (BK / 4)];
        float4 bv = bG[t * (BK / 4)];

        // compute on current buffer
        #pragma unroll
        for (int k = 0; k < BK; k++) {
            ulonglong2 a01 = *reinterpret_cast<const ulonglong2*>(&As2[buf][k][8 * ty]);
            ulonglong2 a23 = *reinterpret_cast<const ulonglong2*>(&As2[buf][k][8 * ty + 4]);
            ulonglong2 b03 = *reinterpret_cast<const ulonglong2*>(&Bs[buf][k][4 * tx]);
            fma2(acc[0][0], a01.x, b03.x); fma2(acc[0][1], a01.x, b03.y);
            fma2(acc[1][0], a01.y, b03.x); fma2(acc[1][1], a01.y, b03.y);
            fma2(acc[2][0], a23.x, b03.x); fma2(acc[2][1], a23.x, b03.y);
            fma2(acc[3][0], a23.y, b03.x); fma2(acc[3][1], a23.y, b03.y);
        }

        // store prefetched chunk into the other buffer (no sync needed before:
        // nobody reads buf^1 until after the barrier below)
        const int nb = buf ^ 1;
        #pragma unroll
        for (int i = 0; i < 4; i++) {
            float va = (&av.x)[i];
            *reinterpret_cast<float2*>(&As2[nb][lc + i][2 * lrow]) = make_float2(va, va);
            Bs[nb][lc + i][lrow] = (&bv.x)[i];
        }
        __syncthreads();
        buf = nb;
    }

    // last chunk
    #pragma unroll
    for (int k = 0; k < BK; k++) {
        ulonglong2 a01 = *reinterpret_cast<const ulonglong2*>(&As2[buf][k][8 * ty]);
        ulonglong2 a23 = *reinterpret_cast<const ulonglong2*>(&As2[buf][k][8 * ty + 4]);
        ulonglong2 b03 = *reinterpret_cast<const ulonglong2*>(&Bs[buf][k][4 * tx]);
        fma2(acc[0][0], a01.x, b03.x); fma2(acc[0][1], a01.x, b03.y);
        fma2(acc[1][0], a01.y, b03.x); fma2(acc[1][1], a01.y, b03.y);
        fma2(acc[2][0], a23.x, b03.x); fma2(acc[2][1], a23.x, b03.y);
        fma2(acc[3][0], a23.y, b03.x); fma2(acc[3][1], a23.y, b03.y);
    }

    // ---- fused epilogue: out = x * wx + bias ----
    const int n = n0 + 4 * tx;
    const float4 bv4 = *reinterpret_cast<const float4*>(bias + n);
    #pragma unroll
    for (int i = 0; i < 4; i++) {
        const int m = m0 + 4 * ty + i;
        float w0, w1, w2, w3;
        asm("mov.b64 {%0, %1}, %2;" : "=f"(w0), "=f"(w1) : "l"(acc[i][0]));
        asm("mov.b64 {%0, %1}, %2;" : "=f"(w2), "=f"(w3) : "l"(acc[i][1]));
        const float4 xv = *reinterpret_cast<const float4*>(X + m * K_DIM + n);
        float4 o;
        o.x = fmaf(xv.x, w0, bv4.x);
        o.y = fmaf(xv.y, w1, bv4.y);
        o.z = fmaf(xv.z, w2, bv4.z);
        o.w = fmaf(xv.w, w3, bv4.w);
        *reinterpret_cast<float4*>(out + m * N_DIM + n) = o;
    }
}

extern "C" void kernel_launch(void* const* d_in, const int* in_sizes, int n_in,
                              void* d_out, int out_size) {
    const float* x    = (const float*)d_in[0];   // (1024, 512)
    const float* w    = (const float*)d_in[1];   // (512, 512)
    const float* bias = (const float*)d_in[2];   // (512,)
    float* out        = (float*)d_out;           // (1024, 512)

    dim3 grid(N_DIM / BN, M_DIM / BM);   // (8, 16) = 128 CTAs
    filp_kernel<<<grid, NTHREADS>>>(x, w, bias, out);
}

// round 4
// speedup vs baseline: 2.7444x; 2.6241x over previous
#include <cuda_runtime.h>
#include <cuda_bf16.h>
#include <cstdint>

#define M_DIM 1024
#define N_DIM 512
#define K_DIM 512

#define BM 64
#define BN 64
#define KC 64                 // bf16 per chunk -> 128B rows (SW128)
#define NCH (K_DIM / KC)      // 8
#define NTHREADS 256

// stage layout (bytes): Ahi 8K | Alo 8K | Bhi 8K | Blo 8K = 32KB, double buffered
#define A_HI 0
#define A_LO 8192
#define B_HI 16384
#define B_LO 24576
#define STAGE 32768
#define SMEM_DYN (2 * STAGE)

// bf16 hi/lo split scratch
__device__ __align__(16) __nv_bfloat16 g_xhi[M_DIM * K_DIM];
__device__ __align__(16) __nv_bfloat16 g_xlo[M_DIM * K_DIM];
__device__ __align__(16) __nv_bfloat16 g_whi[N_DIM * K_DIM];
__device__ __align__(16) __nv_bfloat16 g_wlo[N_DIM * K_DIM];

// ---------------- helpers ----------------
__device__ __forceinline__ uint32_t smem_u32(const void* p) {
    uint32_t a;
    asm("{ .reg .u64 t; cvta.to.shared.u64 t, %1; cvt.u32.u64 %0, t; }"
        : "=r"(a) : "l"(p));
    return a;
}
// SW128: off ^ ((off>>3)&0x70); for off = row*128 + kb (kb<128) this is
// row*128 + (kb ^ ((row&7)<<4))
__device__ __forceinline__ uint32_t sw128(uint32_t off) {
    return off ^ ((off >> 3) & 0x70);
}
__device__ __forceinline__ void cpa16(uint32_t dst, const void* src) {
    asm volatile("cp.async.cg.shared.global [%0], [%1], 16;"
                 :: "r"(dst), "l"(src));
}
__device__ __forceinline__ void ldsm4(uint32_t* r, uint32_t addr) {
    asm volatile("ldmatrix.sync.aligned.m8n8.x4.shared.b16 {%0,%1,%2,%3}, [%4];"
                 : "=r"(r[0]), "=r"(r[1]), "=r"(r[2]), "=r"(r[3]) : "r"(addr));
}
__device__ __forceinline__ void mma_bf16(float* c, const uint32_t* a, const uint32_t* b) {
    asm volatile(
        "mma.sync.aligned.m16n8k16.row.col.f32.bf16.bf16.f32 "
        "{%0,%1,%2,%3}, {%4,%5,%6,%7}, {%8,%9}, {%0,%1,%2,%3};"
        : "+f"(c[0]), "+f"(c[1]), "+f"(c[2]), "+f"(c[3])
        : "r"(a[0]), "r"(a[1]), "r"(a[2]), "r"(a[3]), "r"(b[0]), "r"(b[1]));
}

// ---------------- kernel 1: fp32 -> bf16 hi/lo split ----------------
__global__ void cvt_kernel(const float4* __restrict__ X, const float4* __restrict__ W) {
    const int NX = M_DIM * K_DIM / 4;
    int i = blockIdx.x * 256 + threadIdx.x;
    float4 v;
    uint2 *hd, *ld_;
    if (i < NX) {
        v = X[i];
        hd  = reinterpret_cast<uint2*>(g_xhi) + i;
        ld_ = reinterpret_cast<uint2*>(g_xlo) + i;
    } else {
        int j = i - NX;
        v = W[j];
        hd  = reinterpret_cast<uint2*>(g_whi) + j;
        ld_ = reinterpret_cast<uint2*>(g_wlo) + j;
    }
    __nv_bfloat16 h0 = __float2bfloat16_rn(v.x);
    __nv_bfloat16 h1 = __float2bfloat16_rn(v.y);
    __nv_bfloat16 h2 = __float2bfloat16_rn(v.z);
    __nv_bfloat16 h3 = __float2bfloat16_rn(v.w);
    __nv_bfloat16 l0 = __float2bfloat16_rn(v.x - __bfloat162float(h0));
    __nv_bfloat16 l1 = __float2bfloat16_rn(v.y - __bfloat162float(h1));
    __nv_bfloat16 l2 = __float2bfloat16_rn(v.z - __bfloat162float(h2));
    __nv_bfloat16 l3 = __float2bfloat16_rn(v.w - __bfloat162float(h3));
    __nv_bfloat162 hp0 = __halves2bfloat162(h0, h1);
    __nv_bfloat162 hp1 = __halves2bfloat162(h2, h3);
    __nv_bfloat162 lp0 = __halves2bfloat162(l0, l1);
    __nv_bfloat162 lp1 = __halves2bfloat162(l2, l3);
    uint2 hu, lu;
    hu.x = *reinterpret_cast<uint32_t*>(&hp0);
    hu.y = *reinterpret_cast<uint32_t*>(&hp1);
    lu.x = *reinterpret_cast<uint32_t*>(&lp0);
    lu.y = *reinterpret_cast<uint32_t*>(&lp1);
    *hd  = hu;
    *ld_ = lu;
}

// ---------------- kernel 2: mma.sync GEMM + fused epilogue ----------------
__global__ __launch_bounds__(NTHREADS, 1)
void gemm_kernel(const float* __restrict__ X,
                 const float* __restrict__ bias,
                 float* __restrict__ out)
{
    extern __shared__ char smem[];
    const uint32_t sbase = smem_u32(smem);

    const int tid  = threadIdx.x;
    const int lane = tid & 31;
    const int wid  = tid >> 5;
    const int wm   = (wid & 1) * 32;   // warp M offset (2 groups of 32)
    const int wn   = (wid >> 1) * 16;  // warp N offset (4 groups of 16)

    const int m0 = blockIdx.y * BM;
    const int n0 = blockIdx.x * BN;

    // cp.async loader mapping: 2048 x 16B per stage, 8 per thread
    // region: 0=Ahi 1=Alo 2=Bhi 3=Blo ; 64 rows x 8 16B-units per region
    const __nv_bfloat16* gsrc[4];
    {
        int u0 = tid;                      // region of first unit
        (void)u0;
    }

    float acc[2][2][4];
    #pragma unroll
    for (int a = 0; a < 2; a++)
        #pragma unroll
        for (int b = 0; b < 2; b++)
            #pragma unroll
            for (int q = 0; q < 4; q++)
                acc[a][b][q] = 0.0f;

    // per-lane ldmatrix row/half precomputation
    // A: row = wm + mt*16 + (lane&15), khalf = (lane>>4)&1
    const int arow_l  = lane & 15;
    const int ahalf16 = ((lane >> 4) & 1) * 16;
    // B: row = wn + (lane&7) + ((lane&16)?8:0), khalf = (lane>>3)&1
    const int brow_l  = (lane & 7) + ((lane & 16) ? 8 : 0);
    const int bhalf16 = ((lane >> 3) & 1) * 16;

    // ---- load one chunk (c) into stage st ----
    auto load_chunk = [&](int c, int st) {
        const int kc = c * KC;
        const uint32_t stb = sbase + st * STAGE;
        #pragma unroll
        for (int i = 0; i < 8; i++) {
            int u = i * 256 + tid;            // 0..2047
            int region = u >> 9;              // 0..3
            int r  = (u >> 3) & 63;
            int cu = u & 7;
            const __nv_bfloat16* src;
            if (region == 0)      src = g_xhi + (size_t)(m0 + r) * K_DIM + kc + cu * 8;
            else if (region == 1) src = g_xlo + (size_t)(m0 + r) * K_DIM + kc + cu * 8;
            else if (region == 2) src = g_whi + (size_t)(n0 + r) * K_DIM + kc + cu * 8;
            else                  src = g_wlo + (size_t)(n0 + r) * K_DIM + kc + cu * 8;
            uint32_t dst = stb + region * 8192 + sw128((uint32_t)(r * 128 + cu * 16));
            cpa16(dst, src);
        }
        asm volatile("cp.async.commit_group;" ::: "memory");
    };

    // prologue
    load_chunk(0, 0);

    for (int c = 0; c < NCH; c++) {
        if (c + 1 < NCH) {
            load_chunk(c + 1, (c + 1) & 1);
            asm volatile("cp.async.wait_group 1;" ::: "memory");
        } else {
            asm volatile("cp.async.wait_group 0;" ::: "memory");
        }
        __syncthreads();

        const uint32_t stb = sbase + (c & 1) * STAGE;
        #pragma unroll
        for (int s = 0; s < 4; s++) {
            const uint32_t kb_a = (uint32_t)(s * 32 + ahalf16);
            const uint32_t kb_b = (uint32_t)(s * 32 + bhalf16);

            uint32_t ahi[2][4], alo[2][4], bh[4], bl[4];
            #pragma unroll
            for (int mt = 0; mt < 2; mt++) {
                const uint32_t ra = (uint32_t)(wm + mt * 16 + arow_l);
                const uint32_t ao = ra * 128 + (kb_a ^ ((ra & 7) << 4));
                ldsm4(ahi[mt], stb + A_HI + ao);
                ldsm4(alo[mt], stb + A_LO + ao);
            }
            {
                const uint32_t rb = (uint32_t)(wn + brow_l);
                const uint32_t bo = rb * 128 + (kb_b ^ ((rb & 7) << 4));
                ldsm4(bh, stb + B_HI + bo);
                ldsm4(bl, stb + B_LO + bo);
            }
            #pragma unroll
            for (int mt = 0; mt < 2; mt++) {
                #pragma unroll
                for (int nt = 0; nt < 2; nt++) {
                    mma_bf16(acc[mt][nt], ahi[mt], &bh[2 * nt]);   // hi*hi
                    mma_bf16(acc[mt][nt], ahi[mt], &bl[2 * nt]);   // hi*lo
                    mma_bf16(acc[mt][nt], alo[mt], &bh[2 * nt]);   // lo*hi
                }
            }
        }
        __syncthreads();
    }

    // ---- fused epilogue: out = x * wx + bias ----
    #pragma unroll
    for (int mt = 0; mt < 2; mt++) {
        #pragma unroll
        for (int nt = 0; nt < 2; nt++) {
            const int m = m0 + wm + mt * 16 + (lane >> 2);
            const int n = n0 + wn + nt * 8 + (lane & 3) * 2;
            const float2 bb = *reinterpret_cast<const float2*>(bias + n);
            const float2 x0 = *reinterpret_cast<const float2*>(X + (size_t)m * K_DIM + n);
            const float2 x1 = *reinterpret_cast<const float2*>(X + (size_t)(m + 8) * K_DIM + n);
            float2 o0, o1;
            o0.x = fmaf(x0.x, acc[mt][nt][0], bb.x);
            o0.y = fmaf(x0.y, acc[mt][nt][1], bb.y);
            o1.x = fmaf(x1.x, acc[mt][nt][2], bb.x);
            o1.y = fmaf(x1.y, acc[mt][nt][3], bb.y);
            *reinterpret_cast<float2*>(out + (size_t)m * N_DIM + n) = o0;
            *reinterpret_cast<float2*>(out + (size_t)(m + 8) * N_DIM + n) = o1;
        }
    }
}

// ---------------- launch ----------------
extern "C" void kernel_launch(void* const* d_in, const int* in_sizes, int n_in,
                              void* d_out, int out_size) {
    const float* x    = (const float*)d_in[0];   // (1024, 512)
    const float* w    = (const float*)d_in[1];   // (512, 512)
    const float* bias = (const float*)d_in[2];   // (512,)
    float* out        = (float*)d_out;           // (1024, 512)

    cudaFuncSetAttribute(gemm_kernel, cudaFuncAttributeMaxDynamicSharedMemorySize, SMEM_DYN);

    const int total4 = (M_DIM * K_DIM + N_DIM * K_DIM) / 4;   // 196608
    cvt_kernel<<<total4 / 256, 256>>>((const float4*)x, (const float4*)w);

    dim3 grid(N_DIM / BN, M_DIM / BM);   // (8, 16) = 128 CTAs
    gemm_kernel<<<grid, NTHREADS, SMEM_DYN>>>(x, bias, out);
}